// round 1
// baseline (speedup 1.0000x reference)
#include <cuda_runtime.h>
#include <cuda_bf16.h>
#include <math.h>

// Problem constants
#define SEQ   4096
#define DMODEL 1024
#define NHEAD 16
#define HDIM  64

// Scratch (allocation-free rule: __device__ globals)
__device__ float g_Q[SEQ * DMODEL];
__device__ float g_K[SEQ * DMODEL];
__device__ float g_V[SEQ * DMODEL];
__device__ float g_C[SEQ * DMODEL];

// ---------------------------------------------------------------------------
// SGEMM: C[M,N] = A[M,K] @ B[K,N] (+ bias). 128x128 tile, BK=8, 256 threads,
// 8x8 microtile per thread. M,N,K multiples of 128/128/8.
// ---------------------------------------------------------------------------
__global__ __launch_bounds__(256) void sgemm128(
    const float* __restrict__ A, const float* __restrict__ B,
    const float* __restrict__ bias, float* __restrict__ C,
    int M, int N, int K, int hasBias)
{
    __shared__ float As[8][128];   // [k][m]  (transposed on load)
    __shared__ float Bs[8][128];   // [k][n]

    const int tid = threadIdx.x;
    const int tx = tid & 15;        // 0..15 (n dir)
    const int ty = tid >> 4;        // 0..15 (m dir)
    const int mbase = blockIdx.y * 128;
    const int nbase = blockIdx.x * 128;

    // A-load mapping: 128 rows x 8 cols, 2 threads per row (float4 each)
    const int arow = tid >> 1;            // 0..127
    const int acol = (tid & 1) * 4;       // 0 or 4
    // B-load mapping: 8 rows x 128 cols, 32 threads per row (float4 each)
    const int brow = tid >> 5;            // 0..7
    const int bcol = (tid & 31) * 4;      // 0..124

    float acc[8][8];
#pragma unroll
    for (int i = 0; i < 8; i++)
#pragma unroll
        for (int j = 0; j < 8; j++) acc[i][j] = 0.f;

    for (int k0 = 0; k0 < K; k0 += 8) {
        float4 av = *(const float4*)&A[(size_t)(mbase + arow) * K + k0 + acol];
        As[acol + 0][arow] = av.x;
        As[acol + 1][arow] = av.y;
        As[acol + 2][arow] = av.z;
        As[acol + 3][arow] = av.w;
        *(float4*)&Bs[brow][bcol] =
            *(const float4*)&B[(size_t)(k0 + brow) * N + nbase + bcol];
        __syncthreads();

#pragma unroll
        for (int k = 0; k < 8; k++) {
            float4 a0 = *(const float4*)&As[k][ty * 8];
            float4 a1 = *(const float4*)&As[k][ty * 8 + 4];
            float4 b0 = *(const float4*)&Bs[k][tx * 8];
            float4 b1 = *(const float4*)&Bs[k][tx * 8 + 4];
            float a[8] = {a0.x, a0.y, a0.z, a0.w, a1.x, a1.y, a1.z, a1.w};
            float b[8] = {b0.x, b0.y, b0.z, b0.w, b1.x, b1.y, b1.z, b1.w};
#pragma unroll
            for (int i = 0; i < 8; i++)
#pragma unroll
                for (int j = 0; j < 8; j++)
                    acc[i][j] += a[i] * b[j];
        }
        __syncthreads();
    }

#pragma unroll
    for (int i = 0; i < 8; i++) {
        int m = mbase + ty * 8 + i;
#pragma unroll
        for (int jv = 0; jv < 2; jv++) {
            int n = nbase + tx * 8 + jv * 4;
            float4 v;
            v.x = acc[i][jv * 4 + 0];
            v.y = acc[i][jv * 4 + 1];
            v.z = acc[i][jv * 4 + 2];
            v.w = acc[i][jv * 4 + 3];
            if (hasBias) {
                float4 bv = *(const float4*)&bias[n];
                v.x += bv.x; v.y += bv.y; v.z += bv.z; v.w += bv.w;
            }
            *(float4*)&C[(size_t)m * N + n] = v;
        }
    }
}

// ---------------------------------------------------------------------------
// Flash attention (causal). Block = (head h, q-tile of 64 rows).
// 256 threads (16x16), 4x4 microtile. Online softmax, fp32 accum.
// smem: Qt[d][r], Kt[d][n], V[n][d], Pt[k][r], each 64 x 68 (pad to 68 floats)
// ---------------------------------------------------------------------------
#define SPAD 68
__global__ __launch_bounds__(256) void attn_kernel(
    const float* __restrict__ Q, const float* __restrict__ Kg,
    const float* __restrict__ Vg, float* __restrict__ C)
{
    extern __shared__ float sm[];
    float* Qt = sm;                 // [d][r]   64 x SPAD
    float* Kt = Qt + 64 * SPAD;     // [d][n]
    float* Vs = Kt + 64 * SPAD;     // [n][d]
    float* Pt = Vs + 64 * SPAD;     // [k][r]

    const int h  = blockIdx.y;
    const int qt = blockIdx.x;
    const int tid = threadIdx.x;
    const int tx = tid & 15;
    const int ty = tid >> 4;
    const int qbase = qt * 64;
    const int hcol  = h * HDIM;
    const float scale = 0.125f;     // 1/sqrt(64)

    // Load Q tile transposed: Qt[d][r]
    for (int e = tid; e < 64 * 64; e += 256) {
        int r = e >> 6, d = e & 63;
        Qt[d * SPAD + r] = Q[(size_t)(qbase + r) * DMODEL + hcol + d];
    }

    float m_i[4], l_i[4], O[4][4];
#pragma unroll
    for (int i = 0; i < 4; i++) {
        m_i[i] = -1e30f; l_i[i] = 0.f;
#pragma unroll
        for (int j = 0; j < 4; j++) O[i][j] = 0.f;
    }

    for (int kt = 0; kt <= qt; kt++) {
        const int kbase = kt * 64;
        __syncthreads();   // previous iter's Pt/Vs reads done
        for (int e = tid; e < 64 * 64; e += 256) {
            int n = e >> 6, d = e & 63;
            Kt[d * SPAD + n] = Kg[(size_t)(kbase + n) * DMODEL + hcol + d];
            Vs[n * SPAD + d] = Vg[(size_t)(kbase + n) * DMODEL + hcol + d];
        }
        __syncthreads();

        // S = Q K^T  (4x4 per thread)
        float s[4][4];
#pragma unroll
        for (int i = 0; i < 4; i++)
#pragma unroll
            for (int j = 0; j < 4; j++) s[i][j] = 0.f;

#pragma unroll 8
        for (int d = 0; d < 64; d++) {
            float4 a4 = *(const float4*)&Qt[d * SPAD + ty * 4];
            float4 b4 = *(const float4*)&Kt[d * SPAD + tx * 4];
            float a[4] = {a4.x, a4.y, a4.z, a4.w};
            float b[4] = {b4.x, b4.y, b4.z, b4.w};
#pragma unroll
            for (int i = 0; i < 4; i++)
#pragma unroll
                for (int j = 0; j < 4; j++)
                    s[i][j] += a[i] * b[j];
        }

        const bool diag = (kt == qt);
#pragma unroll
        for (int i = 0; i < 4; i++) {
#pragma unroll
            for (int j = 0; j < 4; j++) {
                float v = s[i][j] * scale;
                if (diag && (kbase + tx * 4 + j) > (qbase + ty * 4 + i)) v = -1e30f;
                s[i][j] = v;
            }
        }

        // online softmax per row (rows owned: ty*4+i, spread across 16 tx lanes)
#pragma unroll
        for (int i = 0; i < 4; i++) {
            float rm = fmaxf(fmaxf(s[i][0], s[i][1]), fmaxf(s[i][2], s[i][3]));
#pragma unroll
            for (int off = 1; off < 16; off <<= 1)
                rm = fmaxf(rm, __shfl_xor_sync(0xffffffffu, rm, off));
            float mn = fmaxf(m_i[i], rm);
            float corr = __expf(m_i[i] - mn);
            m_i[i] = mn;
            l_i[i] *= corr;
#pragma unroll
            for (int j = 0; j < 4; j++) O[i][j] *= corr;
            float rs = 0.f;
#pragma unroll
            for (int j = 0; j < 4; j++) {
                float p = __expf(s[i][j] - mn);
                s[i][j] = p;
                rs += p;
            }
#pragma unroll
            for (int off = 1; off < 16; off <<= 1)
                rs += __shfl_xor_sync(0xffffffffu, rs, off);
            l_i[i] += rs;
        }

        // write P transposed: Pt[k][r]
#pragma unroll
        for (int i = 0; i < 4; i++)
#pragma unroll
            for (int j = 0; j < 4; j++)
                Pt[(tx * 4 + j) * SPAD + ty * 4 + i] = s[i][j];
        __syncthreads();

        // O += P @ V
#pragma unroll 8
        for (int k = 0; k < 64; k++) {
            float4 a4 = *(const float4*)&Pt[k * SPAD + ty * 4];
            float4 b4 = *(const float4*)&Vs[k * SPAD + tx * 4];
            float a[4] = {a4.x, a4.y, a4.z, a4.w};
            float b[4] = {b4.x, b4.y, b4.z, b4.w};
#pragma unroll
            for (int i = 0; i < 4; i++)
#pragma unroll
                for (int j = 0; j < 4; j++)
                    O[i][j] += a[i] * b[j];
        }
    }

    // epilogue
#pragma unroll
    for (int i = 0; i < 4; i++) {
        float inv = 1.f / l_i[i];
        int r = qbase + ty * 4 + i;
        float4 v;
        v.x = O[i][0] * inv; v.y = O[i][1] * inv;
        v.z = O[i][2] * inv; v.w = O[i][3] * inv;
        *(float4*)&C[(size_t)r * DMODEL + hcol + tx * 4] = v;
    }
}

// ---------------------------------------------------------------------------
extern "C" void kernel_launch(void* const* d_in, const int* in_sizes, int n_in,
                              void* d_out, int out_size)
{
    const float* x  = (const float*)d_in[0];
    const float* Wq = (const float*)d_in[1];
    const float* Wk = (const float*)d_in[2];
    const float* Wv = (const float*)d_in[3];
    const float* Wo = (const float*)d_in[4];
    const float* bo = (const float*)d_in[5];
    float* out = (float*)d_out;

    float *Qp, *Kp, *Vp, *Cp;
    cudaGetSymbolAddress((void**)&Qp, g_Q);
    cudaGetSymbolAddress((void**)&Kp, g_K);
    cudaGetSymbolAddress((void**)&Vp, g_V);
    cudaGetSymbolAddress((void**)&Cp, g_C);

    dim3 ggrid(DMODEL / 128, SEQ / 128);   // (8, 32)
    sgemm128<<<ggrid, 256>>>(x, Wq, nullptr, Qp, SEQ, DMODEL, DMODEL, 0);
    sgemm128<<<ggrid, 256>>>(x, Wk, nullptr, Kp, SEQ, DMODEL, DMODEL, 0);
    sgemm128<<<ggrid, 256>>>(x, Wv, nullptr, Vp, SEQ, DMODEL, DMODEL, 0);

    size_t smem = 4 * 64 * SPAD * sizeof(float);   // 69,632 B
    cudaFuncSetAttribute(attn_kernel,
                         cudaFuncAttributeMaxDynamicSharedMemorySize, (int)smem);
    attn_kernel<<<dim3(SEQ / 64, NHEAD), 256, smem>>>(Qp, Kp, Vp, Cp);

    sgemm128<<<ggrid, 256>>>(Cp, Wo, bo, out, SEQ, DMODEL, DMODEL, 1);
}

// round 3
// speedup vs baseline: 5.1348x; 5.1348x over previous
#include <cuda_runtime.h>
#include <cuda_fp16.h>
#include <cstdint>
#include <math.h>

#define SEQ    4096
#define DMODEL 1024
#define NHEAD  16
#define HDIM   64

// ---------------------------------------------------------------------------
// Scratch (__device__ globals; no allocations allowed)
// ---------------------------------------------------------------------------
__device__ __half g_xh[SEQ * DMODEL];
__device__ __half g_Qh[SEQ * DMODEL];
__device__ __half g_Kh[SEQ * DMODEL];
__device__ __half g_Vh[SEQ * DMODEL];
__device__ __half g_Ch[SEQ * DMODEL];
__device__ __half g_WqT[DMODEL * DMODEL];
__device__ __half g_WkT[DMODEL * DMODEL];
__device__ __half g_WvT[DMODEL * DMODEL];
__device__ __half g_WoT[DMODEL * DMODEL];

// ---------------------------------------------------------------------------
// mma / ldmatrix helpers (portable sm_80+ PTX)
// ---------------------------------------------------------------------------
__device__ __forceinline__ uint32_t smem_u32(const void* p) {
    uint32_t a;
    asm("{ .reg .u64 t; cvta.to.shared.u64 t, %1; cvt.u32.u64 %0, t; }"
        : "=r"(a) : "l"(p));
    return a;
}
__device__ __forceinline__ void ldm_x4(uint32_t* r, uint32_t addr) {
    asm volatile("ldmatrix.sync.aligned.m8n8.x4.shared.b16 {%0,%1,%2,%3}, [%4];"
                 : "=r"(r[0]), "=r"(r[1]), "=r"(r[2]), "=r"(r[3]) : "r"(addr));
}
__device__ __forceinline__ void ldm_x4_trans(uint32_t* r, uint32_t addr) {
    asm volatile("ldmatrix.sync.aligned.m8n8.x4.trans.shared.b16 {%0,%1,%2,%3}, [%4];"
                 : "=r"(r[0]), "=r"(r[1]), "=r"(r[2]), "=r"(r[3]) : "r"(addr));
}
__device__ __forceinline__ void mma16816(float* d, const uint32_t* a,
                                         uint32_t b0, uint32_t b1) {
    asm volatile(
        "mma.sync.aligned.m16n8k16.row.col.f32.f16.f16.f32 "
        "{%0,%1,%2,%3}, {%4,%5,%6,%7}, {%8,%9}, {%0,%1,%2,%3};"
        : "+f"(d[0]), "+f"(d[1]), "+f"(d[2]), "+f"(d[3])
        : "r"(a[0]), "r"(a[1]), "r"(a[2]), "r"(a[3]), "r"(b0), "r"(b1));
}
__device__ __forceinline__ uint32_t packh2(float a, float b) {
    __half2 h = __floats2half2_rn(a, b);
    return *reinterpret_cast<uint32_t*>(&h);
}

// ---------------------------------------------------------------------------
// prep: fp32 -> fp16 convert
// ---------------------------------------------------------------------------
__global__ __launch_bounds__(256) void f2h_kernel(
    const float* __restrict__ in, __half* __restrict__ out, int n)
{
    int i = (blockIdx.x * 256 + threadIdx.x) * 4;
    if (i < n) {
        float4 v = *(const float4*)&in[i];
        *(__half2*)&out[i]     = __floats2half2_rn(v.x, v.y);
        *(__half2*)&out[i + 2] = __floats2half2_rn(v.z, v.w);
    }
}

// prep: W[k][n] fp32 -> Wt[n][k] fp16 (optionally scaled)
__global__ __launch_bounds__(256) void transW_kernel(
    const float* __restrict__ in, __half* __restrict__ out, float scale)
{
    __shared__ float t[32][33];
    int tx = threadIdx.x, ty = threadIdx.y;
    int x = blockIdx.x * 32 + tx;       // n
    int y = blockIdx.y * 32 + ty;       // k
#pragma unroll
    for (int j = 0; j < 32; j += 8)
        t[ty + j][tx] = in[(size_t)(y + j) * DMODEL + x];
    __syncthreads();
    int nx = blockIdx.x * 32 + ty;      // n (output row)
    int kx = blockIdx.y * 32 + tx;      // k (output col)
#pragma unroll
    for (int j = 0; j < 32; j += 8)
        out[(size_t)(nx + j) * DMODEL + kx] = __float2half_rn(t[tx][ty + j] * scale);
}

// ---------------------------------------------------------------------------
// GEMM via mma.sync: C[M=4096][N=1024] = A_h[M][K] @ Bt_h[N][K]^T (+bias)
// CTA 128x128, BK=32, 8 warps (2x4), warp tile 64x32. Double-buffered smem.
// ---------------------------------------------------------------------------
#define GK    1024
#define BK    32
#define BKP   40      // padded pitch (80 B = 5*16, conflict-free for ldmatrix)

__global__ __launch_bounds__(256) void gemm_mma(
    const __half* __restrict__ A, const __half* __restrict__ Bt,
    const float* __restrict__ bias,
    float* __restrict__ outF, __half* __restrict__ outH)
{
    __shared__ __align__(16) __half As[2][128][BKP];
    __shared__ __align__(16) __half Bs[2][128][BKP];

    const int tid  = threadIdx.x;
    const int lane = tid & 31;
    const int wid  = tid >> 5;
    const int warp_m = wid >> 2;          // 0..1
    const int warp_n = wid & 3;           // 0..3
    const int mbase = blockIdx.y * 128;
    const int nbase = blockIdx.x * 128;

    // gmem->smem mapping: 512 chunks of 8 halfs; 2 per thread
    const int c0   = tid * 2;
    const int row0 = c0 >> 2, col0 = (c0 & 3) * 8;
    const int row1 = (c0 + 1) >> 2, col1 = ((c0 + 1) & 3) * 8;

    float acc[4][4][4];
#pragma unroll
    for (int i = 0; i < 4; i++)
#pragma unroll
        for (int j = 0; j < 4; j++)
#pragma unroll
            for (int v = 0; v < 4; v++) acc[i][j][v] = 0.f;

    // preload kt=0
    {
        *(uint4*)&As[0][row0][col0] = *(const uint4*)&A[(size_t)(mbase + row0) * GK + col0];
        *(uint4*)&As[0][row1][col1] = *(const uint4*)&A[(size_t)(mbase + row1) * GK + col1];
        *(uint4*)&Bs[0][row0][col0] = *(const uint4*)&Bt[(size_t)(nbase + row0) * GK + col0];
        *(uint4*)&Bs[0][row1][col1] = *(const uint4*)&Bt[(size_t)(nbase + row1) * GK + col1];
    }
    __syncthreads();

    const int NK = GK / BK;   // 32
    for (int kt = 0; kt < NK; kt++) {
        const int s = kt & 1;
        uint4 pa0, pa1, pb0, pb1;
        if (kt + 1 < NK) {
            int koff = (kt + 1) * BK;
            pa0 = *(const uint4*)&A[(size_t)(mbase + row0) * GK + koff + col0];
            pa1 = *(const uint4*)&A[(size_t)(mbase + row1) * GK + koff + col1];
            pb0 = *(const uint4*)&Bt[(size_t)(nbase + row0) * GK + koff + col0];
            pb1 = *(const uint4*)&Bt[(size_t)(nbase + row1) * GK + koff + col1];
        }

#pragma unroll
        for (int ks = 0; ks < 2; ks++) {
            const int k0 = ks * 16;
            uint32_t af[4][4];
#pragma unroll
            for (int mt = 0; mt < 4; mt++) {
                uint32_t addr = smem_u32(
                    &As[s][warp_m * 64 + mt * 16 + (lane & 15)][k0 + 8 * (lane >> 4)]);
                ldm_x4(af[mt], addr);
            }
            uint32_t bf[2][4];
#pragma unroll
            for (int nt2 = 0; nt2 < 2; nt2++) {
                int n0 = warp_n * 32 + nt2 * 16;
                int grp = lane >> 3, lr = lane & 7;
                uint32_t addr = smem_u32(
                    &Bs[s][n0 + (grp >= 2 ? 8 : 0) + lr][k0 + (grp & 1) * 8]);
                ldm_x4(bf[nt2], addr);
            }
#pragma unroll
            for (int mt = 0; mt < 4; mt++)
#pragma unroll
                for (int nt = 0; nt < 4; nt++)
                    mma16816(acc[mt][nt], af[mt],
                             bf[nt >> 1][(nt & 1) * 2], bf[nt >> 1][(nt & 1) * 2 + 1]);
        }

        if (kt + 1 < NK) {
            const int ns = (kt + 1) & 1;
            *(uint4*)&As[ns][row0][col0] = pa0;
            *(uint4*)&As[ns][row1][col1] = pa1;
            *(uint4*)&Bs[ns][row0][col0] = pb0;
            *(uint4*)&Bs[ns][row1][col1] = pb1;
        }
        __syncthreads();
    }

    // epilogue
#pragma unroll
    for (int mt = 0; mt < 4; mt++) {
#pragma unroll
        for (int nt = 0; nt < 4; nt++) {
            int r0 = mbase + warp_m * 64 + mt * 16 + (lane >> 2);
            int cc = nbase + warp_n * 32 + nt * 8 + 2 * (lane & 3);
            float v0 = acc[mt][nt][0], v1 = acc[mt][nt][1];
            float v2 = acc[mt][nt][2], v3 = acc[mt][nt][3];
            if (bias) {
                float2 bv = *(const float2*)&bias[cc];
                v0 += bv.x; v1 += bv.y; v2 += bv.x; v3 += bv.y;
            }
            if (outF) {
                *(float2*)&outF[(size_t)r0 * DMODEL + cc]       = make_float2(v0, v1);
                *(float2*)&outF[(size_t)(r0 + 8) * DMODEL + cc] = make_float2(v2, v3);
            }
            if (outH) {
                *(__half2*)&outH[(size_t)r0 * DMODEL + cc]       = __floats2half2_rn(v0, v1);
                *(__half2*)&outH[(size_t)(r0 + 8) * DMODEL + cc] = __floats2half2_rn(v2, v3);
            }
        }
    }
}

// ---------------------------------------------------------------------------
// Flash attention (causal) with mma.sync. Block = 128 q-rows x 1 head.
// 8 warps, each owns 16 q-rows. K/V tiles of 64 keys. Q pre-scaled by 1/8.
// ---------------------------------------------------------------------------
#define APITCH 72   // 144 B pitch: 16B multiple, conflict-free

__global__ __launch_bounds__(256) void attn_mma(
    const __half* __restrict__ Qh, const __half* __restrict__ Kh,
    const __half* __restrict__ Vh, __half* __restrict__ Ch)
{
    __shared__ __align__(16) __half Qs[128][APITCH];
    __shared__ __align__(16) __half Ks[64][APITCH];
    __shared__ __align__(16) __half Vs[64][APITCH];

    const int qt = gridDim.x - 1 - blockIdx.x;   // heavy tiles first
    const int h  = blockIdx.y;
    const int tid = threadIdx.x, lane = tid & 31, wid = tid >> 5;
    const int qbase = qt * 128;
    const int hcol  = h * HDIM;
    const int m0b = wid * 16;            // warp's q rows within block
    const int gm0 = qbase + m0b;

    // load Q tile (128 x 64 halfs)
#pragma unroll
    for (int i = 0; i < 4; i++) {
        int c = tid + i * 256;           // 1024 chunks
        int r = c >> 3, col = (c & 7) * 8;
        *(uint4*)&Qs[r][col] = *(const uint4*)&Qh[(size_t)(qbase + r) * DMODEL + hcol + col];
    }

    float of[8][4];
    float mrow[2] = {-1e30f, -1e30f}, lrow[2] = {0.f, 0.f};
#pragma unroll
    for (int j = 0; j < 8; j++)
#pragma unroll
        for (int v = 0; v < 4; v++) of[j][v] = 0.f;

    const int nkt = 2 * qt + 2;
    for (int kt = 0; kt < nkt; kt++) {
        const int kbase = kt * 64;
        __syncthreads();
#pragma unroll
        for (int i = 0; i < 2; i++) {
            int c = tid + i * 256;       // 512 chunks each
            int r = c >> 3, col = (c & 7) * 8;
            *(uint4*)&Ks[r][col] = *(const uint4*)&Kh[(size_t)(kbase + r) * DMODEL + hcol + col];
            *(uint4*)&Vs[r][col] = *(const uint4*)&Vh[(size_t)(kbase + r) * DMODEL + hcol + col];
        }
        __syncthreads();

        if (kbase > gm0 + 15) continue;  // fully masked for this warp

        // S = Q K^T  (16 x 64)
        float sf[8][4];
#pragma unroll
        for (int j = 0; j < 8; j++)
#pragma unroll
            for (int v = 0; v < 4; v++) sf[j][v] = 0.f;

#pragma unroll
        for (int ks = 0; ks < 4; ks++) {
            const int k0 = ks * 16;
            uint32_t af[4];
            ldm_x4(af, smem_u32(&Qs[m0b + (lane & 15)][k0 + 8 * (lane >> 4)]));
#pragma unroll
            for (int nt2 = 0; nt2 < 4; nt2++) {
                int n0 = nt2 * 16;
                int grp = lane >> 3, lr = lane & 7;
                uint32_t bf[4];
                ldm_x4(bf, smem_u32(&Ks[n0 + (grp >= 2 ? 8 : 0) + lr][k0 + (grp & 1) * 8]));
                mma16816(sf[nt2 * 2],     af, bf[0], bf[1]);
                mma16816(sf[nt2 * 2 + 1], af, bf[2], bf[3]);
            }
        }

        // causal mask
        if (kbase + 63 > gm0) {
            int r0g = gm0 + (lane >> 2), r1g = r0g + 8;
#pragma unroll
            for (int j = 0; j < 8; j++) {
                int ng = kbase + 8 * j + 2 * (lane & 3);
                if (ng > r0g)     sf[j][0] = -1e30f;
                if (ng + 1 > r0g) sf[j][1] = -1e30f;
                if (ng > r1g)     sf[j][2] = -1e30f;
                if (ng + 1 > r1g) sf[j][3] = -1e30f;
            }
        }

        // online softmax (rows: lane>>2 and +8; quad spread over lane&3)
        float rmax[2] = {-1e30f, -1e30f};
#pragma unroll
        for (int j = 0; j < 8; j++) {
            rmax[0] = fmaxf(rmax[0], fmaxf(sf[j][0], sf[j][1]));
            rmax[1] = fmaxf(rmax[1], fmaxf(sf[j][2], sf[j][3]));
        }
#pragma unroll
        for (int off = 1; off <= 2; off <<= 1) {
            rmax[0] = fmaxf(rmax[0], __shfl_xor_sync(0xffffffffu, rmax[0], off));
            rmax[1] = fmaxf(rmax[1], __shfl_xor_sync(0xffffffffu, rmax[1], off));
        }
        float mn0 = fmaxf(mrow[0], rmax[0]), mn1 = fmaxf(mrow[1], rmax[1]);
        float corr0 = __expf(mrow[0] - mn0), corr1 = __expf(mrow[1] - mn1);
        mrow[0] = mn0; mrow[1] = mn1;

        float rsum[2] = {0.f, 0.f};
#pragma unroll
        for (int j = 0; j < 8; j++) {
            float p0 = __expf(sf[j][0] - mn0), p1 = __expf(sf[j][1] - mn0);
            float p2 = __expf(sf[j][2] - mn1), p3 = __expf(sf[j][3] - mn1);
            sf[j][0] = p0; sf[j][1] = p1; sf[j][2] = p2; sf[j][3] = p3;
            rsum[0] += p0 + p1; rsum[1] += p2 + p3;
        }
#pragma unroll
        for (int off = 1; off <= 2; off <<= 1) {
            rsum[0] += __shfl_xor_sync(0xffffffffu, rsum[0], off);
            rsum[1] += __shfl_xor_sync(0xffffffffu, rsum[1], off);
        }
        lrow[0] = lrow[0] * corr0 + rsum[0];
        lrow[1] = lrow[1] * corr1 + rsum[1];
#pragma unroll
        for (int j = 0; j < 8; j++) {
            of[j][0] *= corr0; of[j][1] *= corr0;
            of[j][2] *= corr1; of[j][3] *= corr1;
        }

        // P -> fp16 A-frags
        uint32_t pa[4][4];
#pragma unroll
        for (int s = 0; s < 4; s++) {
            pa[s][0] = packh2(sf[2 * s][0],     sf[2 * s][1]);
            pa[s][1] = packh2(sf[2 * s][2],     sf[2 * s][3]);
            pa[s][2] = packh2(sf[2 * s + 1][0], sf[2 * s + 1][1]);
            pa[s][3] = packh2(sf[2 * s + 1][2], sf[2 * s + 1][3]);
        }

        // O += P @ V  (V via ldmatrix trans: B-frags with k = key)
#pragma unroll
        for (int j2 = 0; j2 < 8; j2++) {
#pragma unroll
            for (int s2 = 0; s2 < 2; s2++) {
                uint32_t vf[4];
                ldm_x4_trans(vf, smem_u32(&Vs[32 * s2 + lane][8 * j2]));
                mma16816(of[j2], pa[2 * s2],     vf[0], vf[1]);
                mma16816(of[j2], pa[2 * s2 + 1], vf[2], vf[3]);
            }
        }
    }

    // epilogue -> Ch (half)
    float inv0 = 1.f / lrow[0], inv1 = 1.f / lrow[1];
    int r0 = gm0 + (lane >> 2), r1 = r0 + 8;
#pragma unroll
    for (int j2 = 0; j2 < 8; j2++) {
        int cc = hcol + 8 * j2 + 2 * (lane & 3);
        *(__half2*)&Ch[(size_t)r0 * DMODEL + cc] =
            __floats2half2_rn(of[j2][0] * inv0, of[j2][1] * inv0);
        *(__half2*)&Ch[(size_t)r1 * DMODEL + cc] =
            __floats2half2_rn(of[j2][2] * inv1, of[j2][3] * inv1);
    }
}

// ---------------------------------------------------------------------------
extern "C" void kernel_launch(void* const* d_in, const int* in_sizes, int n_in,
                              void* d_out, int out_size)
{
    const float* x  = (const float*)d_in[0];
    const float* Wq = (const float*)d_in[1];
    const float* Wk = (const float*)d_in[2];
    const float* Wv = (const float*)d_in[3];
    const float* Wo = (const float*)d_in[4];
    const float* bo = (const float*)d_in[5];
    float* out = (float*)d_out;

    __half *xh, *Qh, *Kh, *Vh, *Chp, *WqT, *WkT, *WvT, *WoT;
    cudaGetSymbolAddress((void**)&xh,  g_xh);
    cudaGetSymbolAddress((void**)&Qh,  g_Qh);
    cudaGetSymbolAddress((void**)&Kh,  g_Kh);
    cudaGetSymbolAddress((void**)&Vh,  g_Vh);
    cudaGetSymbolAddress((void**)&Chp, g_Ch);
    cudaGetSymbolAddress((void**)&WqT, g_WqT);
    cudaGetSymbolAddress((void**)&WkT, g_WkT);
    cudaGetSymbolAddress((void**)&WvT, g_WvT);
    cudaGetSymbolAddress((void**)&WoT, g_WoT);

    f2h_kernel<<<SEQ * DMODEL / 1024, 256>>>(x, xh, SEQ * DMODEL);
    dim3 tg(32, 32), tb(32, 8);
    transW_kernel<<<tg, tb>>>(Wq, WqT, 0.125f);   // fold 1/sqrt(64)
    transW_kernel<<<tg, tb>>>(Wk, WkT, 1.0f);
    transW_kernel<<<tg, tb>>>(Wv, WvT, 1.0f);
    transW_kernel<<<tg, tb>>>(Wo, WoT, 1.0f);

    dim3 ggrid(DMODEL / 128, SEQ / 128);          // (8, 32)
    gemm_mma<<<ggrid, 256>>>(xh, WqT, nullptr, nullptr, Qh);
    gemm_mma<<<ggrid, 256>>>(xh, WkT, nullptr, nullptr, Kh);
    gemm_mma<<<ggrid, 256>>>(xh, WvT, nullptr, nullptr, Vh);

    attn_mma<<<dim3(SEQ / 128, NHEAD), 256>>>(Qh, Kh, Vh, Chp);

    gemm_mma<<<ggrid, 256>>>(Chp, WoT, bo, out, nullptr);
}

// round 4
// speedup vs baseline: 5.5365x; 1.0782x over previous
#include <cuda_runtime.h>
#include <cuda_fp16.h>
#include <cstdint>
#include <math.h>

#define SEQ    4096
#define DMODEL 1024
#define NHEAD  16
#define HDIM   64

// ---------------------------------------------------------------------------
// Scratch (__device__ globals; no allocations allowed)
// ---------------------------------------------------------------------------
__device__ __half g_xh[SEQ * DMODEL];
__device__ __half g_Qh[SEQ * DMODEL];
__device__ __half g_Kh[SEQ * DMODEL];
__device__ __half g_Vh[SEQ * DMODEL];
__device__ __half g_Ch[SEQ * DMODEL];
__device__ __half g_WqT[DMODEL * DMODEL];
__device__ __half g_WkT[DMODEL * DMODEL];
__device__ __half g_WvT[DMODEL * DMODEL];
__device__ __half g_WoT[DMODEL * DMODEL];

// ---------------------------------------------------------------------------
// PTX helpers (portable sm_80+)
// ---------------------------------------------------------------------------
__device__ __forceinline__ uint32_t smem_u32(const void* p) {
    uint32_t a;
    asm("{ .reg .u64 t; cvta.to.shared.u64 t, %1; cvt.u32.u64 %0, t; }"
        : "=r"(a) : "l"(p));
    return a;
}
#define CP16(s, g) \
    asm volatile("cp.async.cg.shared.global [%0], [%1], 16;" :: "r"(s), "l"(g))
#define CPC() asm volatile("cp.async.commit_group;" ::: "memory")
#define CPW(N) asm volatile("cp.async.wait_group %0;" :: "n"(N) : "memory")

__device__ __forceinline__ void ldm_x4(uint32_t* r, uint32_t addr) {
    asm volatile("ldmatrix.sync.aligned.m8n8.x4.shared.b16 {%0,%1,%2,%3}, [%4];"
                 : "=r"(r[0]), "=r"(r[1]), "=r"(r[2]), "=r"(r[3]) : "r"(addr));
}
__device__ __forceinline__ void ldm_x4_trans(uint32_t* r, uint32_t addr) {
    asm volatile("ldmatrix.sync.aligned.m8n8.x4.trans.shared.b16 {%0,%1,%2,%3}, [%4];"
                 : "=r"(r[0]), "=r"(r[1]), "=r"(r[2]), "=r"(r[3]) : "r"(addr));
}
__device__ __forceinline__ void mma16816(float* d, const uint32_t* a,
                                         uint32_t b0, uint32_t b1) {
    asm volatile(
        "mma.sync.aligned.m16n8k16.row.col.f32.f16.f16.f32 "
        "{%0,%1,%2,%3}, {%4,%5,%6,%7}, {%8,%9}, {%0,%1,%2,%3};"
        : "+f"(d[0]), "+f"(d[1]), "+f"(d[2]), "+f"(d[3])
        : "r"(a[0]), "r"(a[1]), "r"(a[2]), "r"(a[3]), "r"(b0), "r"(b1));
}
__device__ __forceinline__ uint32_t packh2(float a, float b) {
    __half2 h = __floats2half2_rn(a, b);
    return *reinterpret_cast<uint32_t*>(&h);
}

// ---------------------------------------------------------------------------
// prep: fp32 -> fp16
// ---------------------------------------------------------------------------
__global__ __launch_bounds__(256) void f2h_kernel(
    const float* __restrict__ in, __half* __restrict__ out, int n)
{
    int i = (blockIdx.x * 256 + threadIdx.x) * 4;
    if (i < n) {
        float4 v = *(const float4*)&in[i];
        *(__half2*)&out[i]     = __floats2half2_rn(v.x, v.y);
        *(__half2*)&out[i + 2] = __floats2half2_rn(v.z, v.w);
    }
}

// prep: 4 weights transposed+converted in one launch (blockIdx.z selects)
struct TW4 { const float* src[4]; __half* dst[4]; float scl[4]; };
__global__ __launch_bounds__(256) void transW4_kernel(TW4 a)
{
    const int z = blockIdx.z;
    const float* in = a.src[z];
    __half* out = a.dst[z];
    const float scale = a.scl[z];
    __shared__ float t[32][33];
    int tx = threadIdx.x, ty = threadIdx.y;
    int x = blockIdx.x * 32 + tx;
    int y = blockIdx.y * 32 + ty;
#pragma unroll
    for (int j = 0; j < 32; j += 8)
        t[ty + j][tx] = in[(size_t)(y + j) * DMODEL + x];
    __syncthreads();
    int nx = blockIdx.x * 32 + ty;
    int kx = blockIdx.y * 32 + tx;
#pragma unroll
    for (int j = 0; j < 32; j += 8)
        out[(size_t)(nx + j) * DMODEL + kx] = __float2half_rn(t[tx][ty + j] * scale);
}

// ---------------------------------------------------------------------------
// GEMM body via mma.sync, 3-stage cp.async pipeline.
// C[4096][1024] = A[M][K] @ Bt[N][K]^T. CTA 128x128, BK=32, 8 warps 64x32.
// ---------------------------------------------------------------------------
#define GK  1024
#define BK  32
#define BKP 40      // 80 B pitch
#define NSTG 3

__device__ __forceinline__ void gemm_body(
    const __half* __restrict__ A, const __half* __restrict__ Bt,
    const float* __restrict__ bias,
    float* __restrict__ outF, __half* __restrict__ outH, char* smraw)
{
    typedef __half (*Tile)[128][BKP];
    Tile As = (Tile)smraw;
    Tile Bs = (Tile)(smraw + NSTG * 128 * BKP * sizeof(__half));

    const int tid  = threadIdx.x;
    const int lane = tid & 31;
    const int wid  = tid >> 5;
    const int warp_m = wid >> 2;
    const int warp_n = wid & 3;
    const int mbase = blockIdx.y * 128;
    const int nbase = blockIdx.x * 128;

    const int c0 = tid * 2;
    const int rA0 = c0 >> 2, cA0 = (c0 & 3) * 8;
    const int rA1 = (c0 + 1) >> 2, cA1 = ((c0 + 1) & 3) * 8;

    auto issue = [&](int s, int kt) {
        const int ko = kt * BK;
        CP16(smem_u32(&As[s][rA0][cA0]), &A[(size_t)(mbase + rA0) * GK + ko + cA0]);
        CP16(smem_u32(&As[s][rA1][cA1]), &A[(size_t)(mbase + rA1) * GK + ko + cA1]);
        CP16(smem_u32(&Bs[s][rA0][cA0]), &Bt[(size_t)(nbase + rA0) * GK + ko + cA0]);
        CP16(smem_u32(&Bs[s][rA1][cA1]), &Bt[(size_t)(nbase + rA1) * GK + ko + cA1]);
    };

    float acc[4][4][4];
#pragma unroll
    for (int i = 0; i < 4; i++)
#pragma unroll
        for (int j = 0; j < 4; j++)
#pragma unroll
            for (int v = 0; v < 4; v++) acc[i][j][v] = 0.f;

    issue(0, 0); CPC();
    issue(1, 1); CPC();

    const int NK = GK / BK;   // 32
    for (int kt = 0; kt < NK; kt++) {
        const int s = kt % NSTG;
        if (kt + 2 < NK) issue((kt + 2) % NSTG, kt + 2);
        CPC();
        CPW(2);
        __syncthreads();

#pragma unroll
        for (int ks = 0; ks < 2; ks++) {
            const int k0 = ks * 16;
            uint32_t af[4][4];
#pragma unroll
            for (int mt = 0; mt < 4; mt++)
                ldm_x4(af[mt], smem_u32(
                    &As[s][warp_m * 64 + mt * 16 + (lane & 15)][k0 + 8 * (lane >> 4)]));
            uint32_t bf[2][4];
#pragma unroll
            for (int nt2 = 0; nt2 < 2; nt2++) {
                int n0 = warp_n * 32 + nt2 * 16;
                int grp = lane >> 3, lr = lane & 7;
                ldm_x4(bf[nt2], smem_u32(
                    &Bs[s][n0 + (grp >= 2 ? 8 : 0) + lr][k0 + (grp & 1) * 8]));
            }
#pragma unroll
            for (int mt = 0; mt < 4; mt++)
#pragma unroll
                for (int nt = 0; nt < 4; nt++)
                    mma16816(acc[mt][nt], af[mt],
                             bf[nt >> 1][(nt & 1) * 2], bf[nt >> 1][(nt & 1) * 2 + 1]);
        }
        __syncthreads();
    }

#pragma unroll
    for (int mt = 0; mt < 4; mt++) {
#pragma unroll
        for (int nt = 0; nt < 4; nt++) {
            int r0 = mbase + warp_m * 64 + mt * 16 + (lane >> 2);
            int cc = nbase + warp_n * 32 + nt * 8 + 2 * (lane & 3);
            float v0 = acc[mt][nt][0], v1 = acc[mt][nt][1];
            float v2 = acc[mt][nt][2], v3 = acc[mt][nt][3];
            if (bias) {
                float2 bv = *(const float2*)&bias[cc];
                v0 += bv.x; v1 += bv.y; v2 += bv.x; v3 += bv.y;
            }
            if (outF) {
                *(float2*)&outF[(size_t)r0 * DMODEL + cc]       = make_float2(v0, v1);
                *(float2*)&outF[(size_t)(r0 + 8) * DMODEL + cc] = make_float2(v2, v3);
            }
            if (outH) {
                *(__half2*)&outH[(size_t)r0 * DMODEL + cc]       = __floats2half2_rn(v0, v1);
                *(__half2*)&outH[(size_t)(r0 + 8) * DMODEL + cc] = __floats2half2_rn(v2, v3);
            }
        }
    }
}

struct QKVArgs { const __half* Wt[3]; __half* Out[3]; };

__global__ __launch_bounds__(256) void gemm_qkv(const __half* __restrict__ A, QKVArgs args)
{
    extern __shared__ char sm[];
    const int z = blockIdx.z;
    gemm_body(A, args.Wt[z], nullptr, nullptr, args.Out[z], sm);
}

__global__ __launch_bounds__(256) void gemm_out(
    const __half* __restrict__ A, const __half* __restrict__ Bt,
    const float* __restrict__ bias, float* __restrict__ outF)
{
    extern __shared__ char sm[];
    gemm_body(A, Bt, bias, outF, nullptr, sm);
}

// ---------------------------------------------------------------------------
// Flash attention (causal), mma.sync, cp.async double-buffered K/V.
// Block = 128 q-rows x 1 head, 8 warps x 16 rows. Q pre-scaled by log2e/8.
// ---------------------------------------------------------------------------
#define APITCH 72

__global__ __launch_bounds__(256) void attn_mma(
    const __half* __restrict__ Qh, const __half* __restrict__ Kh,
    const __half* __restrict__ Vh, __half* __restrict__ Ch)
{
    extern __shared__ char smraw[];
    typedef __half (*QTile)[APITCH];
    QTile Qs = (QTile)smraw;                                     // 128 x 72
    typedef __half (*KTile)[64][APITCH];
    KTile Ks = (KTile)(smraw + 128 * APITCH * sizeof(__half));   // 2 x 64 x 72
    KTile Vs = (KTile)(smraw + (128 + 2 * 64) * APITCH * sizeof(__half));

    const int qt = gridDim.x - 1 - blockIdx.x;
    const int h  = blockIdx.y;
    const int tid = threadIdx.x, lane = tid & 31, wid = tid >> 5;
    const int qbase = qt * 128;
    const int hcol  = h * HDIM;
    const int m0b = wid * 16;
    const int gm0 = qbase + m0b;

    // cp.async chunk mapping for K/V tiles (64 x 64 halfs = 512 chunks)
    const int kc0 = tid, kr0 = kc0 >> 3, kcol0 = (kc0 & 7) * 8;
    const int kc1 = tid + 256, kr1 = kc1 >> 3, kcol1 = (kc1 & 7) * 8;

    auto issue_kv = [&](int s, int kt) {
        const int kb = kt * 64;
        CP16(smem_u32(&Ks[s][kr0][kcol0]), &Kh[(size_t)(kb + kr0) * DMODEL + hcol + kcol0]);
        CP16(smem_u32(&Ks[s][kr1][kcol1]), &Kh[(size_t)(kb + kr1) * DMODEL + hcol + kcol1]);
        CP16(smem_u32(&Vs[s][kr0][kcol0]), &Vh[(size_t)(kb + kr0) * DMODEL + hcol + kcol0]);
        CP16(smem_u32(&Vs[s][kr1][kcol1]), &Vh[(size_t)(kb + kr1) * DMODEL + hcol + kcol1]);
    };

    issue_kv(0, 0); CPC();

    // load Q tile (plain)
#pragma unroll
    for (int i = 0; i < 4; i++) {
        int c = tid + i * 256;
        int r = c >> 3, col = (c & 7) * 8;
        *(uint4*)&Qs[r][col] = *(const uint4*)&Qh[(size_t)(qbase + r) * DMODEL + hcol + col];
    }

    float of[8][4];
    float mrow[2] = {-1e30f, -1e30f}, lrow[2] = {0.f, 0.f};
#pragma unroll
    for (int j = 0; j < 8; j++)
#pragma unroll
        for (int v = 0; v < 4; v++) of[j][v] = 0.f;

    const int nkt = 2 * qt + 2;
    for (int kt = 0; kt < nkt; kt++) {
        const int kbase = kt * 64;
        const int s = kt & 1;
        if (kt + 1 < nkt) issue_kv(1 - s, kt + 1);
        CPC();
        CPW(1);
        __syncthreads();

        if (kbase <= gm0 + 15) {
            // S = Q K^T (16 x 64)
            float sf[8][4];
#pragma unroll
            for (int j = 0; j < 8; j++)
#pragma unroll
                for (int v = 0; v < 4; v++) sf[j][v] = 0.f;

#pragma unroll
            for (int ks = 0; ks < 4; ks++) {
                const int k0 = ks * 16;
                uint32_t af[4];
                ldm_x4(af, smem_u32(&Qs[m0b + (lane & 15)][k0 + 8 * (lane >> 4)]));
#pragma unroll
                for (int nt2 = 0; nt2 < 4; nt2++) {
                    int n0 = nt2 * 16;
                    int grp = lane >> 3, lr = lane & 7;
                    uint32_t bf[4];
                    ldm_x4(bf, smem_u32(&Ks[s][n0 + (grp >= 2 ? 8 : 0) + lr][k0 + (grp & 1) * 8]));
                    mma16816(sf[nt2 * 2],     af, bf[0], bf[1]);
                    mma16816(sf[nt2 * 2 + 1], af, bf[2], bf[3]);
                }
            }

            if (kbase + 63 > gm0) {
                int r0g = gm0 + (lane >> 2), r1g = r0g + 8;
#pragma unroll
                for (int j = 0; j < 8; j++) {
                    int ng = kbase + 8 * j + 2 * (lane & 3);
                    if (ng > r0g)     sf[j][0] = -1e30f;
                    if (ng + 1 > r0g) sf[j][1] = -1e30f;
                    if (ng > r1g)     sf[j][2] = -1e30f;
                    if (ng + 1 > r1g) sf[j][3] = -1e30f;
                }
            }

            float rmax[2] = {-1e30f, -1e30f};
#pragma unroll
            for (int j = 0; j < 8; j++) {
                rmax[0] = fmaxf(rmax[0], fmaxf(sf[j][0], sf[j][1]));
                rmax[1] = fmaxf(rmax[1], fmaxf(sf[j][2], sf[j][3]));
            }
#pragma unroll
            for (int off = 1; off <= 2; off <<= 1) {
                rmax[0] = fmaxf(rmax[0], __shfl_xor_sync(0xffffffffu, rmax[0], off));
                rmax[1] = fmaxf(rmax[1], __shfl_xor_sync(0xffffffffu, rmax[1], off));
            }
            float mn0 = fmaxf(mrow[0], rmax[0]), mn1 = fmaxf(mrow[1], rmax[1]);
            float corr0 = exp2f(mrow[0] - mn0), corr1 = exp2f(mrow[1] - mn1);
            mrow[0] = mn0; mrow[1] = mn1;

            float rsum[2] = {0.f, 0.f};
#pragma unroll
            for (int j = 0; j < 8; j++) {
                float p0 = exp2f(sf[j][0] - mn0), p1 = exp2f(sf[j][1] - mn0);
                float p2 = exp2f(sf[j][2] - mn1), p3 = exp2f(sf[j][3] - mn1);
                sf[j][0] = p0; sf[j][1] = p1; sf[j][2] = p2; sf[j][3] = p3;
                rsum[0] += p0 + p1; rsum[1] += p2 + p3;
            }
#pragma unroll
            for (int off = 1; off <= 2; off <<= 1) {
                rsum[0] += __shfl_xor_sync(0xffffffffu, rsum[0], off);
                rsum[1] += __shfl_xor_sync(0xffffffffu, rsum[1], off);
            }
            lrow[0] = lrow[0] * corr0 + rsum[0];
            lrow[1] = lrow[1] * corr1 + rsum[1];
#pragma unroll
            for (int j = 0; j < 8; j++) {
                of[j][0] *= corr0; of[j][1] *= corr0;
                of[j][2] *= corr1; of[j][3] *= corr1;
            }

            uint32_t pa[4][4];
#pragma unroll
            for (int t = 0; t < 4; t++) {
                pa[t][0] = packh2(sf[2 * t][0],     sf[2 * t][1]);
                pa[t][1] = packh2(sf[2 * t][2],     sf[2 * t][3]);
                pa[t][2] = packh2(sf[2 * t + 1][0], sf[2 * t + 1][1]);
                pa[t][3] = packh2(sf[2 * t + 1][2], sf[2 * t + 1][3]);
            }

#pragma unroll
            for (int j2 = 0; j2 < 8; j2++) {
#pragma unroll
                for (int s2 = 0; s2 < 2; s2++) {
                    uint32_t vf[4];
                    ldm_x4_trans(vf, smem_u32(&Vs[s][32 * s2 + lane][8 * j2]));
                    mma16816(of[j2], pa[2 * s2],     vf[0], vf[1]);
                    mma16816(of[j2], pa[2 * s2 + 1], vf[2], vf[3]);
                }
            }
        }
        __syncthreads();
    }

    float inv0 = 1.f / lrow[0], inv1 = 1.f / lrow[1];
    int r0 = gm0 + (lane >> 2), r1 = r0 + 8;
#pragma unroll
    for (int j2 = 0; j2 < 8; j2++) {
        int cc = hcol + 8 * j2 + 2 * (lane & 3);
        *(__half2*)&Ch[(size_t)r0 * DMODEL + cc] =
            __floats2half2_rn(of[j2][0] * inv0, of[j2][1] * inv0);
        *(__half2*)&Ch[(size_t)r1 * DMODEL + cc] =
            __floats2half2_rn(of[j2][2] * inv1, of[j2][3] * inv1);
    }
}

// ---------------------------------------------------------------------------
extern "C" void kernel_launch(void* const* d_in, const int* in_sizes, int n_in,
                              void* d_out, int out_size)
{
    const float* x  = (const float*)d_in[0];
    const float* Wq = (const float*)d_in[1];
    const float* Wk = (const float*)d_in[2];
    const float* Wv = (const float*)d_in[3];
    const float* Wo = (const float*)d_in[4];
    const float* bo = (const float*)d_in[5];
    float* out = (float*)d_out;

    __half *xh, *Qh, *Kh, *Vh, *Chp, *WqT, *WkT, *WvT, *WoT;
    cudaGetSymbolAddress((void**)&xh,  g_xh);
    cudaGetSymbolAddress((void**)&Qh,  g_Qh);
    cudaGetSymbolAddress((void**)&Kh,  g_Kh);
    cudaGetSymbolAddress((void**)&Vh,  g_Vh);
    cudaGetSymbolAddress((void**)&Chp, g_Ch);
    cudaGetSymbolAddress((void**)&WqT, g_WqT);
    cudaGetSymbolAddress((void**)&WkT, g_WkT);
    cudaGetSymbolAddress((void**)&WvT, g_WvT);
    cudaGetSymbolAddress((void**)&WoT, g_WoT);

    f2h_kernel<<<SEQ * DMODEL / 1024, 256>>>(x, xh, SEQ * DMODEL);

    TW4 tw;
    tw.src[0] = Wq;  tw.dst[0] = WqT; tw.scl[0] = 0.125f * 1.44269504089f;
    tw.src[1] = Wk;  tw.dst[1] = WkT; tw.scl[1] = 1.0f;
    tw.src[2] = Wv;  tw.dst[2] = WvT; tw.scl[2] = 1.0f;
    tw.src[3] = Wo;  tw.dst[3] = WoT; tw.scl[3] = 1.0f;
    transW4_kernel<<<dim3(32, 32, 4), dim3(32, 8)>>>(tw);

    const int gsmem = NSTG * 128 * BKP * 2 * (int)sizeof(__half);  // 61,440 B
    cudaFuncSetAttribute(gemm_qkv, cudaFuncAttributeMaxDynamicSharedMemorySize, gsmem);
    cudaFuncSetAttribute(gemm_out, cudaFuncAttributeMaxDynamicSharedMemorySize, gsmem);

    QKVArgs qa;
    qa.Wt[0] = WqT; qa.Out[0] = Qh;
    qa.Wt[1] = WkT; qa.Out[1] = Kh;
    qa.Wt[2] = WvT; qa.Out[2] = Vh;
    gemm_qkv<<<dim3(DMODEL / 128, SEQ / 128, 3), 256, gsmem>>>(xh, qa);

    const int asmem = (128 + 4 * 64) * APITCH * (int)sizeof(__half);  // 55,296 B
    cudaFuncSetAttribute(attn_mma, cudaFuncAttributeMaxDynamicSharedMemorySize, asmem);
    attn_mma<<<dim3(SEQ / 128, NHEAD), 256, asmem>>>(Qh, Kh, Vh, Chp);

    gemm_out<<<dim3(DMODEL / 128, SEQ / 128), 256, gsmem>>>(Chp, WoT, bo, out);
}